// round 1
// baseline (speedup 1.0000x reference)
#include <cuda_runtime.h>
#include <cuda_bf16.h>
#include <math.h>

// Problem constants
#define B_   2
#define S_   4096
#define E_   768
#define H_   12
#define DK_  64
#define BH_  (B_ * H_)          // 24
#define ROWS_ (B_ * S_)         // 8192

// ---------------- scratch (device globals; no allocation allowed) -----------
__device__ float g_Q[BH_ * S_ * DK_];    // [bh][s][d], pre-scaled by 1/sqrt(dk)
__device__ float g_K[BH_ * S_ * DK_];
__device__ float g_V[BH_ * S_ * DK_];
__device__ float g_AO[ROWS_ * E_];       // attention output, [b*s][e]

// ---------------- SGEMM: C = A[8192,768] @ W[768,768] -----------------------
// BM=128, BN=128, BK=16, 256 threads, 8x8 microtile.
// mode==1: A=X, W selected by blockIdx.z (Wq/Wk/Wv), scatter to g_Q/g_K/g_V
//          (z==0 scaled by 1/8 = 1/sqrt(64)).
// mode==0: A=g_AO, W=W0 (=Wo), plain row-major store to Out.
#define BM 128
#define BN 128
#define BK 16

__global__ __launch_bounds__(256)
void sgemm_kernel(const float* __restrict__ X,
                  const float* __restrict__ W0,
                  const float* __restrict__ W1,
                  const float* __restrict__ W2,
                  float* __restrict__ Out,
                  int mode)
{
    __shared__ float As[BK][BM + 4];   // A tile, transposed [k][m]
    __shared__ float Bs[BK][BN];       // W tile [k][n]

    const float* A;
    const float* W;
    float* Dst = nullptr;
    float scale = 1.0f;

    if (mode == 1) {
        A = X;
        int z = blockIdx.z;
        W   = (z == 0) ? W0 : (z == 1) ? W1 : W2;
        Dst = (z == 0) ? g_Q : (z == 1) ? g_K : g_V;
        if (z == 0) scale = 0.125f;    // 1/sqrt(64)
    } else {
        A = g_AO;
        W = W0;
    }

    const int tid  = threadIdx.x;
    const int row0 = blockIdx.y * BM;
    const int col0 = blockIdx.x * BN;
    const int tm   = (tid >> 4) * 8;   // 0..120
    const int tn   = (tid & 15) * 8;   // 0..120

    float acc[8][8];
#pragma unroll
    for (int i = 0; i < 8; i++)
#pragma unroll
        for (int j = 0; j < 8; j++) acc[i][j] = 0.0f;

    for (int k0 = 0; k0 < E_; k0 += BK) {
        // load A tile: 128x16 floats = 512 float4
#pragma unroll
        for (int i = 0; i < 2; i++) {
            int idx = tid + i * 256;
            int r   = idx >> 2;        // row in tile
            int c4  = idx & 3;         // which float4 within 16 k's
            float4 v = *(const float4*)&A[(size_t)(row0 + r) * E_ + k0 + c4 * 4];
            As[c4 * 4 + 0][r] = v.x;
            As[c4 * 4 + 1][r] = v.y;
            As[c4 * 4 + 2][r] = v.z;
            As[c4 * 4 + 3][r] = v.w;
        }
        // load W tile: 16x128 floats = 512 float4
#pragma unroll
        for (int i = 0; i < 2; i++) {
            int idx = tid + i * 256;
            int kr  = idx >> 5;        // 32 float4 per 128-col row
            int c4  = idx & 31;
            *(float4*)&Bs[kr][c4 * 4] =
                *(const float4*)&W[(size_t)(k0 + kr) * E_ + col0 + c4 * 4];
        }
        __syncthreads();

#pragma unroll
        for (int k = 0; k < BK; k++) {
            float a[8], b[8];
            *(float4*)&a[0] = *(const float4*)&As[k][tm];
            *(float4*)&a[4] = *(const float4*)&As[k][tm + 4];
            *(float4*)&b[0] = *(const float4*)&Bs[k][tn];
            *(float4*)&b[4] = *(const float4*)&Bs[k][tn + 4];
#pragma unroll
            for (int i = 0; i < 8; i++)
#pragma unroll
                for (int j = 0; j < 8; j++)
                    acc[i][j] += a[i] * b[j];
        }
        __syncthreads();
    }

    if (mode == 1) {
        // scatter into head-major layout [bh][s][d]
        int col = col0 + tn;
        int h   = col >> 6;            // head (8 cols stay within one head)
        int d0  = col & 63;
#pragma unroll
        for (int i = 0; i < 8; i++) {
            int row = row0 + tm + i;
            int b   = row >> 12;
            int s   = row & (S_ - 1);
            float* dst = &Dst[(((size_t)b * H_ + h) * S_ + s) * DK_ + d0];
            float4 v0 = make_float4(acc[i][0] * scale, acc[i][1] * scale,
                                    acc[i][2] * scale, acc[i][3] * scale);
            float4 v1 = make_float4(acc[i][4] * scale, acc[i][5] * scale,
                                    acc[i][6] * scale, acc[i][7] * scale);
            *(float4*)&dst[0] = v0;
            *(float4*)&dst[4] = v1;
        }
    } else {
#pragma unroll
        for (int i = 0; i < 8; i++) {
            int row = row0 + tm + i;
            float* dst = &Out[(size_t)row * E_ + col0 + tn];
            *(float4*)&dst[0] = *(float4*)&acc[i][0];
            *(float4*)&dst[4] = *(float4*)&acc[i][4];
        }
    }
}

// ---------------- flash attention (fp32, online softmax) --------------------
// grid (S/64, BH), 256 threads. BQ = BKV = 64, 4x4 microtile.
// smem: Qs[64][64] | Ks[64][65] | Vs[64][64] | Ps[64][65]
#define ATTN_SMEM ((64 * 64 + 64 * 65 + 64 * 64 + 64 * 65) * 4)

__global__ __launch_bounds__(256)
void attn_kernel()
{
    extern __shared__ float sm[];
    float* Qs = sm;                       // [64][64]   (broadcast reads, no pad)
    float* Ks = Qs + 64 * 64;             // [64][65]
    float* Vs = Ks + 64 * 65;             // [64][64]
    float* Ps = Vs + 64 * 64;             // [64][65]

    const int bh = blockIdx.y;
    const int q0 = blockIdx.x * 64;
    const float* Qg = g_Q + ((size_t)bh * S_ + q0) * DK_;
    const float* Kg = g_K + (size_t)bh * S_ * DK_;
    const float* Vg = g_V + (size_t)bh * S_ * DK_;

    const int tid = threadIdx.x;
    const int ty  = tid >> 4;   // q-row group: rows 4*ty .. 4*ty+3
    const int tx  = tid & 15;   // k-col / d-col group: cols 4*tx .. 4*tx+3

    // load Q tile (64x64 floats = 1024 float4)
#pragma unroll
    for (int i = 0; i < 4; i++) {
        int idx = tid + i * 256;
        ((float4*)Qs)[idx] = ((const float4*)Qg)[idx];
    }

    float m_i[4], l_i[4], O[4][4];
#pragma unroll
    for (int i = 0; i < 4; i++) {
        m_i[i] = -1e30f;
        l_i[i] = 0.0f;
#pragma unroll
        for (int j = 0; j < 4; j++) O[i][j] = 0.0f;
    }

    for (int kt = 0; kt < S_ / 64; kt++) {
        __syncthreads();   // previous iteration's readers of Ks/Vs are done
        // load K tile -> padded smem (scalar stores)
        const float4* K4 = (const float4*)(Kg + (size_t)kt * 64 * DK_);
        const float4* V4 = (const float4*)(Vg + (size_t)kt * 64 * DK_);
#pragma unroll
        for (int i = 0; i < 4; i++) {
            int idx = tid + i * 256;
            int r   = idx >> 4;
            int c4  = idx & 15;
            float4 v = K4[idx];
            Ks[r * 65 + c4 * 4 + 0] = v.x;
            Ks[r * 65 + c4 * 4 + 1] = v.y;
            Ks[r * 65 + c4 * 4 + 2] = v.z;
            Ks[r * 65 + c4 * 4 + 3] = v.w;
            ((float4*)Vs)[idx] = V4[idx];
        }
        __syncthreads();

        // S = Q K^T  (Q pre-scaled by 1/sqrt(dk))
        float s[4][4];
#pragma unroll
        for (int i = 0; i < 4; i++)
#pragma unroll
            for (int j = 0; j < 4; j++) s[i][j] = 0.0f;

#pragma unroll 8
        for (int d = 0; d < DK_; d++) {
            float qv[4];
#pragma unroll
            for (int i = 0; i < 4; i++) qv[i] = Qs[(4 * ty + i) * 64 + d];
#pragma unroll
            for (int j = 0; j < 4; j++) {
                float kv = Ks[(4 * tx + j) * 65 + d];
#pragma unroll
                for (int i = 0; i < 4; i++) s[i][j] += qv[i] * kv;
            }
        }

        // online softmax update (row groups = 16 lanes within a warp)
#pragma unroll
        for (int i = 0; i < 4; i++) {
            float mx = s[i][0];
#pragma unroll
            for (int j = 1; j < 4; j++) mx = fmaxf(mx, s[i][j]);
#pragma unroll
            for (int off = 8; off >= 1; off >>= 1)
                mx = fmaxf(mx, __shfl_xor_sync(0xffffffffu, mx, off, 16));
            float mnew  = fmaxf(m_i[i], mx);
            float alpha = __expf(m_i[i] - mnew);
            float rs = 0.0f;
#pragma unroll
            for (int j = 0; j < 4; j++) {
                float p = __expf(s[i][j] - mnew);
                Ps[(4 * ty + i) * 65 + 4 * tx + j] = p;
                rs += p;
            }
#pragma unroll
            for (int off = 8; off >= 1; off >>= 1)
                rs += __shfl_xor_sync(0xffffffffu, rs, off, 16);
            l_i[i] = l_i[i] * alpha + rs;
            m_i[i] = mnew;
#pragma unroll
            for (int j = 0; j < 4; j++) O[i][j] *= alpha;
        }
        __syncwarp();   // P rows are written/read by the same 16-lane group

        // O += P @ V
#pragma unroll 4
        for (int kk = 0; kk < 64; kk++) {
            float p[4], v[4];
#pragma unroll
            for (int i = 0; i < 4; i++) p[i] = Ps[(4 * ty + i) * 65 + kk];
#pragma unroll
            for (int j = 0; j < 4; j++) v[j] = Vs[kk * 64 + 4 * tx + j];
#pragma unroll
            for (int i = 0; i < 4; i++)
#pragma unroll
                for (int j = 0; j < 4; j++) O[i][j] += p[i] * v[j];
        }
    }

    // epilogue: AO[b*s][h*64 + d]
    const int b = bh / H_;
    const int h = bh % H_;
#pragma unroll
    for (int i = 0; i < 4; i++) {
        float inv = 1.0f / l_i[i];
        int srow = q0 + 4 * ty + i;
        float4 v = make_float4(O[i][0] * inv, O[i][1] * inv,
                               O[i][2] * inv, O[i][3] * inv);
        *(float4*)&g_AO[((size_t)(b * S_ + srow)) * E_ + h * DK_ + 4 * tx] = v;
    }
}

// ---------------- launch -----------------------------------------------------
extern "C" void kernel_launch(void* const* d_in, const int* in_sizes, int n_in,
                              void* d_out, int out_size)
{
    (void)in_sizes; (void)n_in; (void)out_size;
    const float* X  = (const float*)d_in[0];
    const float* Wq = (const float*)d_in[1];
    const float* Wk = (const float*)d_in[2];
    const float* Wv = (const float*)d_in[3];
    const float* Wo = (const float*)d_in[4];
    float* out = (float*)d_out;

    // attribute set is idempotent and not a stream op (capture-safe)
    cudaFuncSetAttribute(attn_kernel,
                         cudaFuncAttributeMaxDynamicSharedMemorySize, ATTN_SMEM);

    // Stage 1: Q/K/V projections (z selects W), head-major scatter, Q pre-scaled
    sgemm_kernel<<<dim3(E_ / BN, ROWS_ / BM, 3), 256>>>(X, Wq, Wk, Wv, nullptr, 1);
    // Stage 2: fused flash attention
    attn_kernel<<<dim3(S_ / 64, BH_), 256, ATTN_SMEM>>>();
    // Stage 3: output projection AO @ Wo -> out
    sgemm_kernel<<<dim3(E_ / BN, ROWS_ / BM, 1), 256>>>(nullptr, Wo, nullptr, nullptr, out, 0);
}

// round 3
// speedup vs baseline: 3.2395x; 3.2395x over previous
#include <cuda_runtime.h>
#include <cuda_bf16.h>
#include <cstdint>
#include <math.h>

// Problem constants
#define B_   2
#define S_   4096
#define E_   768
#define H_   12
#define DK_  64
#define BH_  (B_ * H_)          // 24
#define ROWS_ (B_ * S_)         // 8192

// ---------------- scratch (device globals; no allocation allowed) -----------
__device__ float g_Q[BH_ * S_ * DK_];    // [bh][s][d], pre-scaled by 1/8
__device__ float g_K[BH_ * S_ * DK_];
__device__ float g_V[BH_ * S_ * DK_];
__device__ float g_AO[ROWS_ * E_];       // attention output, [b*s][e]

// ---------------- mma.sync tf32 helpers (generic sm_80+ path) ---------------
__device__ __forceinline__ uint32_t f2tf(float x) {
    uint32_t u;
    asm("cvt.rna.tf32.f32 %0, %1;" : "=r"(u) : "f"(x));
    return u;
}

__device__ __forceinline__ void mma_tf32(float* d,
                                         uint32_t a0, uint32_t a1,
                                         uint32_t a2, uint32_t a3,
                                         uint32_t b0, uint32_t b1) {
    asm volatile(
        "mma.sync.aligned.m16n8k8.row.col.f32.tf32.tf32.f32 "
        "{%0,%1,%2,%3}, {%4,%5,%6,%7}, {%8,%9}, {%0,%1,%2,%3};"
        : "+f"(d[0]), "+f"(d[1]), "+f"(d[2]), "+f"(d[3])
        : "r"(a0), "r"(a1), "r"(a2), "r"(a3), "r"(b0), "r"(b1));
}

// ---------------- GEMM: C = A[8192,768] @ W[768,768] (tf32 mma) -------------
// BM=128, BN=128, BK=16. 8 warps as 2x4, warp tile 64x32 (4x4 m16n8 frags).
// mode==1: A=X, W/Dst by blockIdx.z (scatter head-major, z==0 scaled 1/8).
// mode==0: A=g_AO, W=W0, plain store to Out.
#define AP 20    // As row stride (words), 20 % 32 == 20 -> frag banks (20c+j) distinct
#define BP 136   // Bs row stride, 136 % 32 == 8 -> frag banks (8j+c) distinct

__global__ __launch_bounds__(256, 2)
void gemm_tc(const float* __restrict__ X,
             const float* __restrict__ W0,
             const float* __restrict__ W1,
             const float* __restrict__ W2,
             float* __restrict__ Out,
             int mode)
{
    __shared__ uint32_t As[128 * AP];   // [m][k] row-major, pad
    __shared__ uint32_t Bs[16 * BP];    // [k][n] row-major, pad

    const float* A;
    const float* W;
    float* Dst = nullptr;
    float scale = 1.0f;
    if (mode == 1) {
        A = X;
        int z = blockIdx.z;
        W   = (z == 0) ? W0 : (z == 1) ? W1 : W2;
        Dst = (z == 0) ? g_Q : (z == 1) ? g_K : g_V;
        if (z == 0) scale = 0.125f;
    } else {
        A = g_AO;
        W = W0;
    }

    const int tid  = threadIdx.x;
    const int lane = tid & 31;
    const int wid  = tid >> 5;
    const int wm   = wid >> 2;          // 0..1 -> m offset wm*64
    const int wn   = wid & 3;           // 0..3 -> n offset wn*32
    const int cq   = lane >> 2;         // 0..7
    const int j    = lane & 3;          // 0..3
    const int row0 = blockIdx.y * 128;
    const int col0 = blockIdx.x * 128;

    float acc[4][4][4];
#pragma unroll
    for (int mi = 0; mi < 4; mi++)
#pragma unroll
        for (int ni = 0; ni < 4; ni++)
#pragma unroll
            for (int q = 0; q < 4; q++) acc[mi][ni][q] = 0.0f;

    for (int k0 = 0; k0 < E_; k0 += 16) {
        // A tile: 128x16 -> 512 float4
#pragma unroll
        for (int i = 0; i < 2; i++) {
            int idx = tid + i * 256;
            int r   = idx >> 2;
            int c4  = idx & 3;
            float4 v = *(const float4*)&A[(size_t)(row0 + r) * E_ + k0 + c4 * 4];
            uint4 u = make_uint4(f2tf(v.x), f2tf(v.y), f2tf(v.z), f2tf(v.w));
            *(uint4*)&As[r * AP + c4 * 4] = u;
        }
        // B tile: 16x128 -> 512 float4
#pragma unroll
        for (int i = 0; i < 2; i++) {
            int idx = tid + i * 256;
            int kr  = idx >> 5;
            int c4  = idx & 31;
            float4 v = *(const float4*)&W[(size_t)(k0 + kr) * E_ + col0 + c4 * 4];
            uint4 u = make_uint4(f2tf(v.x), f2tf(v.y), f2tf(v.z), f2tf(v.w));
            *(uint4*)&Bs[kr * BP + c4 * 4] = u;
        }
        __syncthreads();

#pragma unroll
        for (int ks = 0; ks < 16; ks += 8) {
            uint32_t af[4][4], bf[4][2];
#pragma unroll
            for (int mi = 0; mi < 4; mi++) {
                int row = wm * 64 + mi * 16 + cq;
                int ka  = ks + j;
                af[mi][0] = As[row * AP + ka];
                af[mi][1] = As[(row + 8) * AP + ka];
                af[mi][2] = As[row * AP + ka + 4];
                af[mi][3] = As[(row + 8) * AP + ka + 4];
            }
#pragma unroll
            for (int ni = 0; ni < 4; ni++) {
                int col = wn * 32 + ni * 8 + cq;
                bf[ni][0] = Bs[(ks + j) * BP + col];
                bf[ni][1] = Bs[(ks + 4 + j) * BP + col];
            }
#pragma unroll
            for (int mi = 0; mi < 4; mi++)
#pragma unroll
                for (int ni = 0; ni < 4; ni++)
                    mma_tf32(acc[mi][ni], af[mi][0], af[mi][1], af[mi][2], af[mi][3],
                             bf[ni][0], bf[ni][1]);
        }
        __syncthreads();
    }

    // epilogue: C frag rows r, r+8 (r = lane>>2), cols 2j, 2j+1
#pragma unroll
    for (int mi = 0; mi < 4; mi++) {
#pragma unroll
        for (int ni = 0; ni < 4; ni++) {
            int r_   = row0 + wm * 64 + mi * 16 + cq;
            int col  = col0 + wn * 32 + ni * 8 + 2 * j;
            float2 v0 = make_float2(acc[mi][ni][0] * scale, acc[mi][ni][1] * scale);
            float2 v1 = make_float2(acc[mi][ni][2] * scale, acc[mi][ni][3] * scale);
            if (mode == 1) {
                int h  = col >> 6;
                int d0 = col & 63;
                int b0b = r_ >> 12, s0s = r_ & (S_ - 1);
                *(float2*)&Dst[(((size_t)b0b * H_ + h) * S_ + s0s) * DK_ + d0] = v0;
                int r1 = r_ + 8;
                int b1b = r1 >> 12, s1s = r1 & (S_ - 1);
                *(float2*)&Dst[(((size_t)b1b * H_ + h) * S_ + s1s) * DK_ + d0] = v1;
            } else {
                *(float2*)&Out[(size_t)r_ * E_ + col] = v0;
                *(float2*)&Out[(size_t)(r_ + 8) * E_ + col] = v1;
            }
        }
    }
}

// ---------------- flash attention on mma.sync tf32 --------------------------
// CTA: 128 q-rows x 1 head, 8 warps (warp = 16 q rows), KV tile 64.
// Smem (dynamic): Qs[128][68], Ks[64][68], Vs[64][72]  (uint32 tf32 bits)
#define QP 68
#define KP 68
#define VP 72
#define QS_OFF 0
#define KS_OFF (128 * QP)                 // 8704
#define VS_OFF (KS_OFF + 64 * KP)         // 13056
#define ATTN_SMEM ((VS_OFF + 64 * VP) * 4)  // 70656 bytes

__global__ __launch_bounds__(256, 2)
void attn_tc_kernel()
{
    extern __shared__ uint32_t sm[];
    uint32_t* Qs = sm + QS_OFF;
    uint32_t* Ks = sm + KS_OFF;
    uint32_t* Vs = sm + VS_OFF;

    const int tid  = threadIdx.x;
    const int lane = tid & 31;
    const int wid  = tid >> 5;
    const int cq   = lane >> 2;          // 0..7 within quad rows
    const int j    = lane & 3;
    const int bh   = blockIdx.y;
    const int q0   = blockIdx.x * 128;
    const int wq   = wid * 16;           // warp's q-row offset in tile

    const float4* Qg = (const float4*)(g_Q + ((size_t)bh * S_ + q0) * DK_);
    const float4* Kg = (const float4*)(g_K + (size_t)bh * S_ * DK_);
    const float4* Vg = (const float4*)(g_V + (size_t)bh * S_ * DK_);

    // load Q tile: 128x64 = 2048 float4
#pragma unroll
    for (int i = 0; i < 8; i++) {
        int idx = tid + i * 256;
        int r   = idx >> 4;
        int c4  = idx & 15;
        float4 v = Qg[idx];
        uint4 u = make_uint4(f2tf(v.x), f2tf(v.y), f2tf(v.z), f2tf(v.w));
        *(uint4*)&Qs[r * QP + c4 * 4] = u;
    }

    float m0 = -1e30f, m1 = -1e30f, l0 = 0.0f, l1 = 0.0f;
    float o[8][4];
#pragma unroll
    for (int d = 0; d < 8; d++)
#pragma unroll
        for (int q = 0; q < 4; q++) o[d][q] = 0.0f;

    for (int kt = 0; kt < S_ / 64; kt++) {
        __syncthreads();
        // load K,V tiles: 64x64 each = 1024 float4 each
#pragma unroll
        for (int i = 0; i < 4; i++) {
            int idx = tid + i * 256;
            int r   = idx >> 4;
            int c4  = idx & 15;
            float4 kv = Kg[kt * 1024 + idx];
            *(uint4*)&Ks[r * KP + c4 * 4] =
                make_uint4(f2tf(kv.x), f2tf(kv.y), f2tf(kv.z), f2tf(kv.w));
            float4 vv = Vg[kt * 1024 + idx];
            *(uint4*)&Vs[r * VP + c4 * 4] =
                make_uint4(f2tf(vv.x), f2tf(vv.y), f2tf(vv.z), f2tf(vv.w));
        }
        __syncthreads();

        // ---- S = Q @ K^T : 8 n-tiles (kv cols), 8 k-blocks (dk) ------------
        float p[8][4];
#pragma unroll
        for (int t = 0; t < 8; t++)
#pragma unroll
            for (int q = 0; q < 4; q++) p[t][q] = 0.0f;

#pragma unroll
        for (int kb = 0; kb < 8; kb++) {
            int row = wq + cq;
            int ka  = kb * 8 + j;
            uint32_t a0 = Qs[row * QP + ka];
            uint32_t a1 = Qs[(row + 8) * QP + ka];
            uint32_t a2 = Qs[row * QP + ka + 4];
            uint32_t a3 = Qs[(row + 8) * QP + ka + 4];
#pragma unroll
            for (int t = 0; t < 8; t++) {
                uint32_t b0 = Ks[(t * 8 + cq) * KP + ka];
                uint32_t b1 = Ks[(t * 8 + cq) * KP + ka + 4];
                mma_tf32(p[t], a0, a1, a2, a3, b0, b1);
            }
        }

        // ---- online softmax (rows r=wq+cq and r+8) -------------------------
        float mx0 = p[0][0], mx1 = p[0][2];
#pragma unroll
        for (int t = 0; t < 8; t++) {
            mx0 = fmaxf(mx0, fmaxf(p[t][0], p[t][1]));
            mx1 = fmaxf(mx1, fmaxf(p[t][2], p[t][3]));
        }
        mx0 = fmaxf(mx0, __shfl_xor_sync(0xffffffffu, mx0, 1));
        mx0 = fmaxf(mx0, __shfl_xor_sync(0xffffffffu, mx0, 2));
        mx1 = fmaxf(mx1, __shfl_xor_sync(0xffffffffu, mx1, 1));
        mx1 = fmaxf(mx1, __shfl_xor_sync(0xffffffffu, mx1, 2));

        float mn0 = fmaxf(m0, mx0), mn1 = fmaxf(m1, mx1);
        float al0 = __expf(m0 - mn0), al1 = __expf(m1 - mn1);
        m0 = mn0; m1 = mn1;

        // exp, round P to tf32, accumulate row sums from the ROUNDED values
        uint32_t pt[8][4];
        float rs0 = 0.0f, rs1 = 0.0f;
#pragma unroll
        for (int t = 0; t < 8; t++) {
            float e;
            e = __expf(p[t][0] - mn0); pt[t][0] = f2tf(e); rs0 += __uint_as_float(pt[t][0]);
            e = __expf(p[t][1] - mn0); pt[t][1] = f2tf(e); rs0 += __uint_as_float(pt[t][1]);
            e = __expf(p[t][2] - mn1); pt[t][2] = f2tf(e); rs1 += __uint_as_float(pt[t][2]);
            e = __expf(p[t][3] - mn1); pt[t][3] = f2tf(e); rs1 += __uint_as_float(pt[t][3]);
        }
        rs0 += __shfl_xor_sync(0xffffffffu, rs0, 1);
        rs0 += __shfl_xor_sync(0xffffffffu, rs0, 2);
        rs1 += __shfl_xor_sync(0xffffffffu, rs1, 1);
        rs1 += __shfl_xor_sync(0xffffffffu, rs1, 2);
        l0 = l0 * al0 + rs0;
        l1 = l1 * al1 + rs1;

        // rescale O
#pragma unroll
        for (int d = 0; d < 8; d++) {
            o[d][0] *= al0; o[d][1] *= al0;
            o[d][2] *= al1; o[d][3] *= al1;
        }

        // ---- O += P @ V : transform C-frag -> A-frag via shuffles ----------
#pragma unroll
        for (int kb = 0; kb < 8; kb++) {
            int s0 = (lane & 28) | (j >> 1);
            int s2 = s0 + 2;
            uint32_t q00 = __shfl_sync(0xffffffffu, pt[kb][0], s0);
            uint32_t q01 = __shfl_sync(0xffffffffu, pt[kb][1], s0);
            uint32_t q20 = __shfl_sync(0xffffffffu, pt[kb][2], s0);
            uint32_t q21 = __shfl_sync(0xffffffffu, pt[kb][3], s0);
            uint32_t r00 = __shfl_sync(0xffffffffu, pt[kb][0], s2);
            uint32_t r01 = __shfl_sync(0xffffffffu, pt[kb][1], s2);
            uint32_t r20 = __shfl_sync(0xffffffffu, pt[kb][2], s2);
            uint32_t r21 = __shfl_sync(0xffffffffu, pt[kb][3], s2);
            uint32_t ap0 = (j & 1) ? q01 : q00;
            uint32_t ap1 = (j & 1) ? q21 : q20;
            uint32_t ap2 = (j & 1) ? r01 : r00;
            uint32_t ap3 = (j & 1) ? r21 : r20;
#pragma unroll
            for (int d = 0; d < 8; d++) {
                uint32_t b0 = Vs[(kb * 8 + j) * VP + d * 8 + cq];
                uint32_t b1 = Vs[(kb * 8 + 4 + j) * VP + d * 8 + cq];
                mma_tf32(o[d], ap0, ap1, ap2, ap3, b0, b1);
            }
        }
    }

    // ---- epilogue: AO[b*s][h*64 + d] ---------------------------------------
    const float inv0 = 1.0f / l0, inv1 = 1.0f / l1;
    const int b = bh / H_, h = bh % H_;
    int r_ = q0 + wq + cq;
#pragma unroll
    for (int d = 0; d < 8; d++) {
        int col = h * DK_ + d * 8 + 2 * j;
        *(float2*)&g_AO[(size_t)(b * S_ + r_) * E_ + col] =
            make_float2(o[d][0] * inv0, o[d][1] * inv0);
        *(float2*)&g_AO[(size_t)(b * S_ + r_ + 8) * E_ + col] =
            make_float2(o[d][2] * inv1, o[d][3] * inv1);
    }
}

// ---------------- launch -----------------------------------------------------
extern "C" void kernel_launch(void* const* d_in, const int* in_sizes, int n_in,
                              void* d_out, int out_size)
{
    (void)in_sizes; (void)n_in; (void)out_size;
    const float* X  = (const float*)d_in[0];
    const float* Wq = (const float*)d_in[1];
    const float* Wk = (const float*)d_in[2];
    const float* Wv = (const float*)d_in[3];
    const float* Wo = (const float*)d_in[4];
    float* out = (float*)d_out;

    cudaFuncSetAttribute(attn_tc_kernel,
                         cudaFuncAttributeMaxDynamicSharedMemorySize, ATTN_SMEM);

    // Stage 1: Q/K/V projections (head-major scatter, Q pre-scaled by 1/8)
    gemm_tc<<<dim3(E_ / 128, ROWS_ / 128, 3), 256>>>(X, Wq, Wk, Wv, nullptr, 1);
    // Stage 2: tf32 mma flash attention
    attn_tc_kernel<<<dim3(S_ / 128, BH_), 256, ATTN_SMEM>>>();
    // Stage 3: output projection AO @ Wo -> out
    gemm_tc<<<dim3(E_ / 128, ROWS_ / 128, 1), 256>>>(nullptr, Wo, nullptr, nullptr, out, 0);
}